// round 11
// baseline (speedup 1.0000x reference)
#include <cuda_runtime.h>
#include <math.h>
#include <stdint.h>

// Problem constants
#define B_   8
#define S_   1024
#define H_   16
#define LAT_ 1024
#define D_   64

// ---------------------------------------------------------------------------
// Scratch (__device__ globals: allocation-free rule)
// ---------------------------------------------------------------------------
__device__ float g_Q[(size_t)B_ * H_ * S_ * D_];   // [bh, s, d]
__device__ float g_K[(size_t)B_ * H_ * S_ * D_];   // [bh, s, d]
__device__ float g_V[(size_t)B_ * H_ * S_ * D_];   // [bh, s, d]
__device__ float g_O[(size_t)B_ * S_ * H_ * D_];   // [b*s, h*d]

// ---------------------------------------------------------------------------
// mma.sync m16n8k8 tf32 helpers (compute_80+)
// Fragment maps (PTX ISA), g = lane>>2, t = lane&3:
//   A(16x8):  a0=(g,t) a1=(g+8,t) a2=(g,t+4) a3=(g+8,t+4)
//   B(8x8):   b0=(t,g) b1=(t+4,g)
//   D(16x8):  d0=(g,2t) d1=(g,2t+1) d2=(g+8,2t) d3=(g+8,2t+1)
// ---------------------------------------------------------------------------
__device__ __forceinline__ void mma_tf32(float* d, const uint32_t* a,
                                         uint32_t b0, uint32_t b1) {
    asm volatile(
        "mma.sync.aligned.m16n8k8.row.col.f32.tf32.tf32.f32 "
        "{%0,%1,%2,%3}, {%4,%5,%6,%7}, {%8,%9}, {%0,%1,%2,%3};"
        : "+f"(d[0]), "+f"(d[1]), "+f"(d[2]), "+f"(d[3])
        : "r"(a[0]), "r"(a[1]), "r"(a[2]), "r"(a[3]), "r"(b0), "r"(b1));
}

__device__ __forceinline__ float to_tf32(float x) {
    uint32_t u;
    asm("cvt.rna.tf32.f32 %0, %1;" : "=r"(u) : "f"(x));
    return __uint_as_float(u);
}

__device__ __forceinline__ float4 to_tf32_4(float4 v) {
    v.x = to_tf32(v.x); v.y = to_tf32(v.y);
    v.z = to_tf32(v.z); v.w = to_tf32(v.w);
    return v;
}

__device__ __forceinline__ uint32_t fbits(float x) { return __float_as_uint(x); }

// cp.async (Ampere+, no "a"-feature)
__device__ __forceinline__ void cp16(uint32_t dst, const void* src) {
    asm volatile("cp.async.cg.shared.global [%0], [%1], 16;\n"
                 :: "r"(dst), "l"(src));
}
#define CP_COMMIT() asm volatile("cp.async.commit_group;\n" ::: "memory")
#define CP_WAIT2()  asm volatile("cp.async.wait_group 2;\n" ::: "memory")

// ---------------------------------------------------------------------------
// TF32 tensor-core GEMM: C = A[M,1024] @ W[1024,N] + bias
// Tile 128x128, BK=16, cp.async 4-stage pipeline: one sync + one wait_group
// per k-step, no register staging, no STS on the critical path.
// tf32 rounding applied at fragment-load time (identical values to before).
// As stride 20 / Bs stride 136: conflict-free fragment LDS (verified).
// ---------------------------------------------------------------------------
#define AST 20
#define BST 136
#define AS_BYTES    (128 * AST * 4)            /* 10240 */
#define BS_BYTES    (16 * BST * 4)             /* 8704  */
#define STAGE_BYTES (AS_BYTES + BS_BYTES)      /* 18944 */
#define GEMM_SMEM   (4 * STAGE_BYTES)          /* 75776 */

template <int OUT_BHSD>
__global__ __launch_bounds__(256, 2)
void gemm_mma(const float* __restrict__ A, const float* __restrict__ W,
              const float* __restrict__ bias, float* __restrict__ C)
{
    extern __shared__ __align__(16) char gsm[];

    const int tid  = threadIdx.x;
    const int lane = tid & 31;
    const int wid  = tid >> 5;
    const int g = lane >> 2, t = lane & 3;
    const int wm = (wid & 1) * 64;
    const int wn = (wid >> 1) * 32;
    const int m0 = blockIdx.y * 128;
    const int n0 = blockIdx.x * 128;

    // Per-thread copy map: 2 A float4 + 2 B float4 per stage
    const int arow0 = tid >> 2,         ac0 = (tid & 3) * 4;
    const int arow1 = (tid + 256) >> 2, ac1 = ac0;
    const int brow0 = tid >> 5,         bc0 = (tid & 31) * 4;
    const int brow1 = brow0 + 8;
    const float* gA0 = A + (size_t)(m0 + arow0) * LAT_ + ac0;
    const float* gA1 = A + (size_t)(m0 + arow1) * LAT_ + ac1;
    const float* gB0 = W + (size_t)brow0 * LAT_ + n0 + bc0;
    const float* gB1 = W + (size_t)brow1 * LAT_ + n0 + bc0;
    const uint32_t sbase = (uint32_t)__cvta_generic_to_shared(gsm);
    const uint32_t dA0 = (arow0 * AST + ac0) * 4;
    const uint32_t dA1 = (arow1 * AST + ac1) * 4;
    const uint32_t dB0 = AS_BYTES + (brow0 * BST + bc0) * 4;
    const uint32_t dB1 = AS_BYTES + (brow1 * BST + bc0) * 4;

    float acc[4][4][4];
#pragma unroll
    for (int i = 0; i < 4; i++)
#pragma unroll
        for (int j = 0; j < 4; j++)
#pragma unroll
            for (int r = 0; r < 4; r++) acc[i][j][r] = 0.0f;

    // Prologue: stages 0..2 in flight
#pragma unroll
    for (int s = 0; s < 3; s++) {
        uint32_t buf = sbase + s * STAGE_BYTES;
        cp16(buf + dA0, gA0 + s * 16);
        cp16(buf + dA1, gA1 + s * 16);
        cp16(buf + dB0, gB0 + (size_t)(s * 16) * LAT_);
        cp16(buf + dB1, gB1 + (size_t)(s * 16) * LAT_);
        CP_COMMIT();
    }

    for (int kt = 0; kt < 64; kt++) {
        CP_WAIT2();            // group kt complete (<=2 newer pending)
        __syncthreads();       // all warps see stage kt; all done with kt-1
        if (kt + 3 < 64) {     // issue stage kt+3 (buffer (kt+3)&3 != kt&3)
            uint32_t buf = sbase + ((kt + 3) & 3) * STAGE_BYTES;
            cp16(buf + dA0, gA0 + (kt + 3) * 16);
            cp16(buf + dA1, gA1 + (kt + 3) * 16);
            cp16(buf + dB0, gB0 + (size_t)((kt + 3) * 16) * LAT_);
            cp16(buf + dB1, gB1 + (size_t)((kt + 3) * 16) * LAT_);
        }
        CP_COMMIT();           // commit every iteration (empty ok) for bookkeeping

        const float* As = (const float*)(gsm + (size_t)(kt & 3) * STAGE_BYTES);
        const float* Bs = (const float*)(gsm + (size_t)(kt & 3) * STAGE_BYTES + AS_BYTES);
#pragma unroll
        for (int ks = 0; ks < 2; ks++) {
            uint32_t a[4][4], b[4][2];
#pragma unroll
            for (int i = 0; i < 4; i++) {
                int base = (wm + i * 16 + g) * AST + ks * 8 + t;
                a[i][0] = fbits(to_tf32(As[base]));
                a[i][1] = fbits(to_tf32(As[base + 8 * AST]));
                a[i][2] = fbits(to_tf32(As[base + 4]));
                a[i][3] = fbits(to_tf32(As[base + 8 * AST + 4]));
            }
#pragma unroll
            for (int j = 0; j < 4; j++) {
                int base = (ks * 8 + t) * BST + wn + j * 8 + g;
                b[j][0] = fbits(to_tf32(Bs[base]));
                b[j][1] = fbits(to_tf32(Bs[base + 4 * BST]));
            }
#pragma unroll
            for (int i = 0; i < 4; i++)
#pragma unroll
                for (int j = 0; j < 4; j++)
                    mma_tf32(acc[i][j], a[i], b[j][0], b[j][1]);
        }
    }

    // Epilogue: fragment-direct float2 stores (+bias)
#pragma unroll
    for (int i = 0; i < 4; i++) {
        int r0 = m0 + wm + i * 16 + g;
#pragma unroll
        for (int j = 0; j < 4; j++) {
            int n = n0 + wn + j * 8 + 2 * t;
            float2 bb = *(const float2*)&bias[n];
            float2 v0 = { acc[i][j][0] + bb.x, acc[i][j][1] + bb.y };
            float2 v1 = { acc[i][j][2] + bb.x, acc[i][j][3] + bb.y };
            if (!OUT_BHSD) {
                *(float2*)(C + (size_t)r0 * LAT_ + n)       = v0;
                *(float2*)(C + (size_t)(r0 + 8) * LAT_ + n) = v1;
            } else {
                int bi = r0 >> 10, s = r0 & 1023;
                int h = n >> 6, d = n & 63;
                *(float2*)(C + (((size_t)(bi * H_ + h)) * S_ + s) * D_ + d)     = v0;
                *(float2*)(C + (((size_t)(bi * H_ + h)) * S_ + s + 8) * D_ + d) = v1;
            }
        }
    }
}

// ---------------------------------------------------------------------------
// Tensor-core flash attention (round-7 structure + shfl-built P fragments).
// Block: 128 queries, 256 threads (8 warps); warp w owns rows [16w, 16w+16).
// Smem (67584 B, 2 CTAs/SM):
//   Qf [wid][ks][lane] float4  A-frags of Q    (32 KB) -> LDS.128
//   Kf B-frags of QK^T (17408 B) | Vf B-frags of PV (17408 B), stride 68.
// P never touches smem: its A-frags are built from score registers by
// quad-shfl (lane mapping verified in round 8).
// exp2-domain softmax (scores pre-scaled by 0.125*log2 e).
// ---------------------------------------------------------------------------
#define QF_OFF   0
#define KF_OFF   32768
#define VF_OFF   (32768 + 17408)
#define QTMP_OFF 32768                   /* transient 34816B = Kf+Vf region */
#define ATTN_SMEM (32768 + 2 * 17408)    /* 67584 B */
#define SCL 0.1803368801111244f   /* 0.125 * log2(e) */

__global__ __launch_bounds__(256, 2)
void attn_mma_kernel(const int* __restrict__ mask, float* __restrict__ Og)
{
    extern __shared__ __align__(16) char smem[];
    float* Qf   = (float*)(smem + QF_OFF);
    float* Kf   = (float*)(smem + KF_OFF);
    float* Vf   = (float*)(smem + VF_OFF);
    float* Qtmp = (float*)(smem + QTMP_OFF);

    const int tid  = threadIdx.x;
    const int lane = tid & 31;
    const int wid  = tid >> 5;
    const int g = lane >> 2, t = lane & 3;
    const int qbase = blockIdx.x * 128;
    const int bh    = blockIdx.y;
    const int wq    = wid * 16;

    // --- Stage Q row-major (tf32) into transient area (128 x 68) ---
    const float* Qp = g_Q + ((size_t)bh * S_ + qbase) * D_;
#pragma unroll
    for (int it = 0; it < 8; it++) {
        int idx = tid + it * 256;
        int row = idx >> 4, c4 = (idx & 15) * 4;
        *(float4*)&Qtmp[row * 68 + c4] =
            to_tf32_4(*(const float4*)(Qp + (size_t)row * D_ + c4));
    }
    __syncthreads();

    // --- Fragment-major Qf (reads conflict-free: bank 4g+t) ---
#pragma unroll
    for (int ks = 0; ks < 8; ks++) {
        float q0 = Qtmp[(wq + g) * 68 + ks * 8 + t];
        float q1 = Qtmp[(wq + g + 8) * 68 + ks * 8 + t];
        float q2 = Qtmp[(wq + g) * 68 + ks * 8 + t + 4];
        float q3 = Qtmp[(wq + g + 8) * 68 + ks * 8 + t + 4];
        float4 f = { q0, q1, q2, q3 };
        *(float4*)&Qf[wid * 1024 + ks * 128 + lane * 4] = f;
    }
    __syncthreads();   // Qtmp dead; Kf/Vf live from here

    float m0r = -INFINITY, m1r = -INFINITY, l0 = 0.0f, l1 = 0.0f;
    float oacc[8][4];
#pragma unroll
    for (int nt = 0; nt < 8; nt++)
#pragma unroll
        for (int r = 0; r < 4; r++) oacc[nt][r] = 0.0f;

    const int* mrow0 = mask + ((size_t)bh * S_ + (qbase + wq + g)) * S_;
    const int* mrow1 = mrow0 + 8 * S_;

    // V staging map (fixed per thread)
    const int vrp = tid >> 3, vc = tid & 7;
    const int vks = vrp >> 2, vt = vrp & 3, vr = vks * 8 + vt;

    // Shfl-P lane mapping (verified in round 8)
    const int srcA = (lane & 28) + (t >> 1);
    const int srcB = srcA + 2;
    const bool odd = (t & 1);

    for (int kt = 0; kt < 16; kt++) {
        const int kbase = kt * 64;

        // Mask prefetch for this tile (latency hidden behind staging + MMAs)
        int2 mk0[8], mk1[8];
#pragma unroll
        for (int nt = 0; nt < 8; nt++) {
            mk0[nt] = *(const int2*)&mrow0[kbase + nt * 8 + 2 * t];
            mk1[nt] = *(const int2*)&mrow1[kbase + nt * 8 + 2 * t];
        }

        // --- Stage K in fragment-pair order: 2 items/thread ---
#pragma unroll
        for (int it = 0; it < 2; it++) {
            int item = tid + it * 256;          // 0..511
            int r = item >> 3, c = item & 7;
            const float* gk = g_K + ((size_t)bh * S_ + kbase + r) * D_ + c * 8;
            float4 v0 = to_tf32_4(*(const float4*)gk);
            float4 v1 = to_tf32_4(*(const float4*)(gk + 4));
            float* dst = Kf + ((r >> 3) * 8 + c) * 68 + (r & 7) * 8;
            float4 w0 = { v0.x, v1.x, v0.y, v1.y };
            float4 w1 = { v0.z, v1.z, v0.w, v1.w };
            *(float4*)(dst)     = w0;
            *(float4*)(dst + 4) = w1;
        }
        // --- Stage V: row pair (vr, vr+4), 8-col block vc ---
        {
            const float* gv = g_V + ((size_t)bh * S_ + kbase + vr) * D_ + vc * 8;
            float4 a0 = to_tf32_4(*(const float4*)gv);
            float4 a1 = to_tf32_4(*(const float4*)(gv + 4));
            float4 b0 = to_tf32_4(*(const float4*)(gv + 4 * D_));
            float4 b1 = to_tf32_4(*(const float4*)(gv + 4 * D_ + 4));
            float* dst = Vf + (vks * 8 + vc) * 68 + vt * 2;
            float2 p;
            p.x = a0.x; p.y = b0.x; *(float2*)(dst + 0)  = p;
            p.x = a0.y; p.y = b0.y; *(float2*)(dst + 8)  = p;
            p.x = a0.z; p.y = b0.z; *(float2*)(dst + 16) = p;
            p.x = a0.w; p.y = b0.w; *(float2*)(dst + 24) = p;
            p.x = a1.x; p.y = b1.x; *(float2*)(dst + 32) = p;
            p.x = a1.y; p.y = b1.y; *(float2*)(dst + 40) = p;
            p.x = a1.z; p.y = b1.z; *(float2*)(dst + 48) = p;
            p.x = a1.w; p.y = b1.w; *(float2*)(dst + 56) = p;
        }
        __syncthreads();

        // --- S = Q @ K^T ---
        float sacc[8][4];
#pragma unroll
        for (int nt = 0; nt < 8; nt++)
#pragma unroll
            for (int r = 0; r < 4; r++) sacc[nt][r] = 0.0f;
#pragma unroll
        for (int ks = 0; ks < 8; ks++) {
            uint4 qf = *(const uint4*)&Qf[wid * 1024 + ks * 128 + lane * 4];
            uint32_t qa_[4] = { qf.x, qf.y, qf.z, qf.w };
#pragma unroll
            for (int nt = 0; nt < 8; nt++) {
                float2 kf = *(const float2*)&Kf[(nt * 8 + ks) * 68 + lane * 2];
                mma_tf32(sacc[nt], qa_, fbits(kf.x), fbits(kf.y));
            }
        }

        // --- Mask + exp2-scale, row maxima ---
        float rm0 = -INFINITY, rm1 = -INFINITY;
#pragma unroll
        for (int nt = 0; nt < 8; nt++) {
            sacc[nt][0] = mk0[nt].x ? sacc[nt][0] * SCL : -INFINITY;
            sacc[nt][1] = mk0[nt].y ? sacc[nt][1] * SCL : -INFINITY;
            sacc[nt][2] = mk1[nt].x ? sacc[nt][2] * SCL : -INFINITY;
            sacc[nt][3] = mk1[nt].y ? sacc[nt][3] * SCL : -INFINITY;
            rm0 = fmaxf(rm0, fmaxf(sacc[nt][0], sacc[nt][1]));
            rm1 = fmaxf(rm1, fmaxf(sacc[nt][2], sacc[nt][3]));
        }
#pragma unroll
        for (int off = 1; off <= 2; off <<= 1) {
            rm0 = fmaxf(rm0, __shfl_xor_sync(0xffffffffu, rm0, off));
            rm1 = fmaxf(rm1, __shfl_xor_sync(0xffffffffu, rm1, off));
        }
        float mn0 = fmaxf(m0r, rm0);
        float mn1 = fmaxf(m1r, rm1);
        float corr0 = (mn0 == -INFINITY) ? 1.0f : exp2f(m0r - mn0);
        float corr1 = (mn1 == -INFINITY) ? 1.0f : exp2f(m1r - mn1);
        m0r = mn0; m1r = mn1;

        // --- exp2 into sacc (P values stay in registers), row sums ---
        float rs0 = 0.0f, rs1 = 0.0f;
#pragma unroll
        for (int nt = 0; nt < 8; nt++) {
            float p0 = (sacc[nt][0] == -INFINITY) ? 0.0f : exp2f(sacc[nt][0] - mn0);
            float p1 = (sacc[nt][1] == -INFINITY) ? 0.0f : exp2f(sacc[nt][1] - mn0);
            float p2 = (sacc[nt][2] == -INFINITY) ? 0.0f : exp2f(sacc[nt][2] - mn1);
            float p3 = (sacc[nt][3] == -INFINITY) ? 0.0f : exp2f(sacc[nt][3] - mn1);
            sacc[nt][0] = p0; sacc[nt][1] = p1;
            sacc[nt][2] = p2; sacc[nt][3] = p3;
            rs0 += p0 + p1;  rs1 += p2 + p3;
        }
#pragma unroll
        for (int off = 1; off <= 2; off <<= 1) {
            rs0 += __shfl_xor_sync(0xffffffffu, rs0, off);
            rs1 += __shfl_xor_sync(0xffffffffu, rs1, off);
        }
        l0 = l0 * corr0 + rs0;
        l1 = l1 * corr1 + rs1;
#pragma unroll
        for (int nt = 0; nt < 8; nt++) {
            oacc[nt][0] *= corr0; oacc[nt][1] *= corr0;
            oacc[nt][2] *= corr1; oacc[nt][3] *= corr1;
        }

        // --- O += P @ V : P A-frags built by quad-shfl from score regs ---
#pragma unroll
        for (int ks = 0; ks < 8; ks++) {
            float a0 = __shfl_sync(0xffffffffu, sacc[ks][0], srcA);
            float a1 = __shfl_sync(0xffffffffu, sacc[ks][1], srcA);
            float a2 = __shfl_sync(0xffffffffu, sacc[ks][2], srcA);
            float a3 = __shfl_sync(0xffffffffu, sacc[ks][3], srcA);
            float b0 = __shfl_sync(0xffffffffu, sacc[ks][0], srcB);
            float b1 = __shfl_sync(0xffffffffu, sacc[ks][1], srcB);
            float b2 = __shfl_sync(0xffffffffu, sacc[ks][2], srcB);
            float b3 = __shfl_sync(0xffffffffu, sacc[ks][3], srcB);
            uint32_t pa_[4] = { fbits(odd ? a1 : a0), fbits(odd ? a3 : a2),
                                fbits(odd ? b1 : b0), fbits(odd ? b3 : b2) };
#pragma unroll
            for (int nt = 0; nt < 8; nt++) {
                float2 vf = *(const float2*)&Vf[(ks * 8 + nt) * 68 + lane * 2];
                mma_tf32(oacc[nt], pa_, fbits(vf.x), fbits(vf.y));
            }
        }
        __syncthreads();   // Kf/Vf reads done before next tile's staging
    }

    // --- Final normalize + write [b*s][h*64+d] ---
    const int b = bh >> 4;
    const int h = bh & 15;
    const int r0 = qbase + wq + g;
    float inv0 = 1.0f / l0, inv1 = 1.0f / l1;
#pragma unroll
    for (int nt = 0; nt < 8; nt++) {
        int col = h * D_ + nt * 8 + 2 * t;
        float2 v0 = { oacc[nt][0] * inv0, oacc[nt][1] * inv0 };
        float2 v1 = { oacc[nt][2] * inv1, oacc[nt][3] * inv1 };
        *(float2*)(Og + ((size_t)(b * S_ + r0)) * (H_ * D_) + col)     = v0;
        *(float2*)(Og + ((size_t)(b * S_ + r0 + 8)) * (H_ * D_) + col) = v1;
    }
}

// ---------------------------------------------------------------------------
// Launch
// ---------------------------------------------------------------------------
extern "C" void kernel_launch(void* const* d_in, const int* in_sizes, int n_in,
                              void* d_out, int out_size)
{
    const float* input  = (const float*)d_in[0];
    const float* latent = (const float*)d_in[1];
    const int*   mask   = (const int*)d_in[2];
    const float* Wq = (const float*)d_in[3];
    const float* bq = (const float*)d_in[4];
    const float* Wk = (const float*)d_in[5];
    const float* bk = (const float*)d_in[6];
    const float* Wv = (const float*)d_in[7];
    const float* bv = (const float*)d_in[8];
    const float* Wo = (const float*)d_in[9];
    const float* bo = (const float*)d_in[10];
    float* out = (float*)d_out;

    float *qp, *kp, *vp, *op;
    cudaGetSymbolAddress((void**)&qp, g_Q);
    cudaGetSymbolAddress((void**)&kp, g_K);
    cudaGetSymbolAddress((void**)&vp, g_V);
    cudaGetSymbolAddress((void**)&op, g_O);

    cudaFuncSetAttribute(gemm_mma<0>,
                         cudaFuncAttributeMaxDynamicSharedMemorySize, GEMM_SMEM);
    cudaFuncSetAttribute(gemm_mma<1>,
                         cudaFuncAttributeMaxDynamicSharedMemorySize, GEMM_SMEM);
    cudaFuncSetAttribute(attn_mma_kernel,
                         cudaFuncAttributeMaxDynamicSharedMemorySize, ATTN_SMEM);

    dim3 gg(LAT_ / 128, (B_ * S_) / 128);   // (8, 64)
    gemm_mma<1><<<gg, 256, GEMM_SMEM>>>(latent, Wq, bq, qp);
    gemm_mma<1><<<gg, 256, GEMM_SMEM>>>(input,  Wk, bk, kp);
    gemm_mma<1><<<gg, 256, GEMM_SMEM>>>(input,  Wv, bv, vp);

    dim3 ga(S_ / 128, B_ * H_);             // (8, 128)
    attn_mma_kernel<<<ga, 256, ATTN_SMEM>>>(mask, op);

    gemm_mma<0><<<gg, 256, GEMM_SMEM>>>(op, Wo, bo, out);
}

// round 15
// speedup vs baseline: 1.1642x; 1.1642x over previous
#include <cuda_runtime.h>
#include <cuda_fp16.h>
#include <math.h>
#include <stdint.h>

#define B_   8
#define S_   1024
#define H_   16
#define LAT_ 1024
#define D_   64

// ---------------------------------------------------------------------------
// Scratch: Q/K f16 [bh][s][d]; V f16 [bh][d][s] (transposed); O f32 [m][h*d]
// ---------------------------------------------------------------------------
__device__ __half g_Q[(size_t)B_ * H_ * S_ * D_];
__device__ __half g_K[(size_t)B_ * H_ * S_ * D_];
__device__ __half g_V[(size_t)B_ * H_ * S_ * D_];
__device__ float  g_O[(size_t)B_ * S_ * H_ * D_];

// ---------------------------------------------------------------------------
// MMA helpers. g = lane>>2, t = lane&3.
// tf32 m16n8k8 (GEMM): A a0=(g,t) a1=(g+8,t) a2=(g,t+4) a3=(g+8,t+4);
//                      B b0=(t,g) b1=(t+4,g); D d0=(g,2t) d1=(g,2t+1) d2/d3 +8row
// f16 m16n8k16 (attn): A a0=(g,2t:2t+1) a1=(g+8,..) a2=(g,2t+8:+9) a3=(g+8,..)
//                      B b0=(2t:2t+1,g) b1=(2t+8:+9,g); D same as above
// ---------------------------------------------------------------------------
__device__ __forceinline__ void mma_tf32(float* d, const uint32_t* a,
                                         uint32_t b0, uint32_t b1) {
    asm volatile(
        "mma.sync.aligned.m16n8k8.row.col.f32.tf32.tf32.f32 "
        "{%0,%1,%2,%3}, {%4,%5,%6,%7}, {%8,%9}, {%0,%1,%2,%3};"
        : "+f"(d[0]), "+f"(d[1]), "+f"(d[2]), "+f"(d[3])
        : "r"(a[0]), "r"(a[1]), "r"(a[2]), "r"(a[3]), "r"(b0), "r"(b1));
}
__device__ __forceinline__ void mma_f16(float* d, const uint32_t* a,
                                        uint32_t b0, uint32_t b1) {
    asm volatile(
        "mma.sync.aligned.m16n8k16.row.col.f32.f16.f16.f32 "
        "{%0,%1,%2,%3}, {%4,%5,%6,%7}, {%8,%9}, {%0,%1,%2,%3};"
        : "+f"(d[0]), "+f"(d[1]), "+f"(d[2]), "+f"(d[3])
        : "r"(a[0]), "r"(a[1]), "r"(a[2]), "r"(a[3]), "r"(b0), "r"(b1));
}
__device__ __forceinline__ float to_tf32(float x) {
    uint32_t u;
    asm("cvt.rna.tf32.f32 %0, %1;" : "=r"(u) : "f"(x));
    return __uint_as_float(u);
}
__device__ __forceinline__ uint32_t fbits(float x) { return __float_as_uint(x); }
__device__ __forceinline__ uint32_t packh2(float lo, float hi) {
    __half2 h = __floats2half2_rn(lo, hi);
    return *(uint32_t*)&h;
}
__device__ __forceinline__ void cp16(uint32_t dst, const void* src) {
    asm volatile("cp.async.cg.shared.global [%0], [%1], 16;\n" :: "r"(dst), "l"(src));
}
#define CP_COMMIT() asm volatile("cp.async.commit_group;\n" ::: "memory")
#define CP_WAIT0()  asm volatile("cp.async.wait_group 0;\n" ::: "memory")
#define CP_WAIT1()  asm volatile("cp.async.wait_group 1;\n" ::: "memory")
#define CP_WAIT2()  asm volatile("cp.async.wait_group 2;\n" ::: "memory")

// ---------------------------------------------------------------------------
// TF32 GEMM (mainloop identical to round 10): C = A @ W + bias.
// OUT: 0 = f32 [m][n]; 1 = f16 [bh][s][d]; 2 = f16 [bh][d][s] (V transposed).
// ---------------------------------------------------------------------------
#define AST 20
#define BST 136
#define AS_BYTES    (128 * AST * 4)
#define BS_BYTES    (16 * BST * 4)
#define STAGE_BYTES (AS_BYTES + BS_BYTES)
#define GEMM_SMEM   (4 * STAGE_BYTES)

template <int OUT>
__global__ __launch_bounds__(256, 2)
void gemm_mma(const float* __restrict__ A, const float* __restrict__ W,
              const float* __restrict__ bias, void* __restrict__ Cp)
{
    extern __shared__ __align__(16) char gsm[];

    const int tid  = threadIdx.x;
    const int lane = tid & 31;
    const int wid  = tid >> 5;
    const int g = lane >> 2, t = lane & 3;
    const int wm = (wid & 1) * 64;
    const int wn = (wid >> 1) * 32;
    const int m0 = blockIdx.y * 128;
    const int n0 = blockIdx.x * 128;

    const int arow0 = tid >> 2,         ac0 = (tid & 3) * 4;
    const int arow1 = (tid + 256) >> 2;
    const int brow0 = tid >> 5,         bc0 = (tid & 31) * 4;
    const int brow1 = brow0 + 8;
    const float* gA0 = A + (size_t)(m0 + arow0) * LAT_ + ac0;
    const float* gA1 = A + (size_t)(m0 + arow1) * LAT_ + ac0;
    const float* gB0 = W + (size_t)brow0 * LAT_ + n0 + bc0;
    const float* gB1 = W + (size_t)brow1 * LAT_ + n0 + bc0;
    const uint32_t sbase = (uint32_t)__cvta_generic_to_shared(gsm);
    const uint32_t dA0 = (arow0 * AST + ac0) * 4;
    const uint32_t dA1 = (arow1 * AST + ac0) * 4;
    const uint32_t dB0 = AS_BYTES + (brow0 * BST + bc0) * 4;
    const uint32_t dB1 = AS_BYTES + (brow1 * BST + bc0) * 4;

    float acc[4][4][4];
#pragma unroll
    for (int i = 0; i < 4; i++)
#pragma unroll
        for (int j = 0; j < 4; j++)
#pragma unroll
            for (int r = 0; r < 4; r++) acc[i][j][r] = 0.0f;

#pragma unroll
    for (int s = 0; s < 3; s++) {
        uint32_t buf = sbase + s * STAGE_BYTES;
        cp16(buf + dA0, gA0 + s * 16);
        cp16(buf + dA1, gA1 + s * 16);
        cp16(buf + dB0, gB0 + (size_t)(s * 16) * LAT_);
        cp16(buf + dB1, gB1 + (size_t)(s * 16) * LAT_);
        CP_COMMIT();
    }

    for (int kt = 0; kt < 64; kt++) {
        CP_WAIT2();
        __syncthreads();
        if (kt + 3 < 64) {
            uint32_t buf = sbase + ((kt + 3) & 3) * STAGE_BYTES;
            cp16(buf + dA0, gA0 + (kt + 3) * 16);
            cp16(buf + dA1, gA1 + (kt + 3) * 16);
            cp16(buf + dB0, gB0 + (size_t)((kt + 3) * 16) * LAT_);
            cp16(buf + dB1, gB1 + (size_t)((kt + 3) * 16) * LAT_);
        }
        CP_COMMIT();

        const float* As = (const float*)(gsm + (size_t)(kt & 3) * STAGE_BYTES);
        const float* Bs = (const float*)(gsm + (size_t)(kt & 3) * STAGE_BYTES + AS_BYTES);
#pragma unroll
        for (int ks = 0; ks < 2; ks++) {
            uint32_t a[4][4], b[4][2];
#pragma unroll
            for (int i = 0; i < 4; i++) {
                int base = (wm + i * 16 + g) * AST + ks * 8 + t;
                a[i][0] = fbits(to_tf32(As[base]));
                a[i][1] = fbits(to_tf32(As[base + 8 * AST]));
                a[i][2] = fbits(to_tf32(As[base + 4]));
                a[i][3] = fbits(to_tf32(As[base + 8 * AST + 4]));
            }
#pragma unroll
            for (int j = 0; j < 4; j++) {
                int base = (ks * 8 + t) * BST + wn + j * 8 + g;
                b[j][0] = fbits(to_tf32(Bs[base]));
                b[j][1] = fbits(to_tf32(Bs[base + 4 * BST]));
            }
#pragma unroll
            for (int i = 0; i < 4; i++)
#pragma unroll
                for (int j = 0; j < 4; j++)
                    mma_tf32(acc[i][j], a[i], b[j][0], b[j][1]);
        }
    }

#pragma unroll
    for (int i = 0; i < 4; i++) {
        int r0 = m0 + wm + i * 16 + g;
#pragma unroll
        for (int j = 0; j < 4; j++) {
            int n = n0 + wn + j * 8 + 2 * t;
            float2 bb = *(const float2*)&bias[n];
            float2 v0 = { acc[i][j][0] + bb.x, acc[i][j][1] + bb.y };
            float2 v1 = { acc[i][j][2] + bb.x, acc[i][j][3] + bb.y };
            int bi = r0 >> 10, s = r0 & 1023;
            int h = n >> 6, d = n & 63;
            if (OUT == 0) {
                float* C = (float*)Cp;
                *(float2*)(C + (size_t)r0 * LAT_ + n)       = v0;
                *(float2*)(C + (size_t)(r0 + 8) * LAT_ + n) = v1;
            } else if (OUT == 1) {
                __half* C = (__half*)Cp;
                size_t base = (((size_t)(bi * H_ + h)) * S_ + s) * D_ + d;
                *(uint32_t*)&C[base]          = packh2(v0.x, v0.y);
                *(uint32_t*)&C[base + 8 * D_] = packh2(v1.x, v1.y);
            } else {
                __half* C = (__half*)Cp;   // [bh][d][s]
                size_t base = ((size_t)(bi * H_ + h) * D_ + d) * S_ + s;
                C[base]           = __float2half_rn(v0.x);
                C[base + S_]      = __float2half_rn(v0.y);
                C[base + 8]       = __float2half_rn(v1.x);
                C[base + S_ + 8]  = __float2half_rn(v1.y);
            }
        }
    }
}

// ---------------------------------------------------------------------------
// fp16 flash attention. 128 q/block, 8 warps (16 q/warp), 2 CTAs/SM.
// Smem 53248B: Qf 16KB frag-major | K/V double-buffered 2x18432B, row stride
// 72 halves (conflict-free frag LDS.32). K/V staged by cp.async (raw f16).
// P A-frags = own-lane score regs packed to half2 (no shfl, no smem).
// ---------------------------------------------------------------------------
#define KST_H     72
#define KS_BYTES2 (64 * KST_H * 2)          /* 9216  */
#define TILE_B    (2 * KS_BYTES2)           /* 18432 */
#define ATTN_SMEM (16384 + 2 * TILE_B)      /* 53248 */
#define SCL 0.1803368801111244f             /* 0.125 * log2(e) */

__global__ __launch_bounds__(256, 2)
void attn_mma_kernel(const int* __restrict__ mask, float* __restrict__ Og)
{
    extern __shared__ __align__(16) char smem[];
    const uint32_t sb    = (uint32_t)__cvta_generic_to_shared(smem);
    const uint32_t sb_kv = sb + 16384;

    const int tid  = threadIdx.x;
    const int lane = tid & 31;
    const int wid  = tid >> 5;
    const int g = lane >> 2, t = lane & 3;
    const int qbase = blockIdx.x * 128;
    const int bh    = blockIdx.y;
    const int wq    = wid * 16;

    const __half* gKb = g_K + (size_t)bh * S_ * D_;
    const __half* gVb = g_V + (size_t)bh * D_ * S_;

    // --- Stage Q (raw f16) into transient rows-72 area over stage0, then
    //     gather into fragment-major Qf (uint4 per (wid,ks,lane)) ---
    {
        const __half* gQb = g_Q + ((size_t)bh * S_ + qbase) * D_;
        __half* Qtmp = (__half*)(smem + 16384);
#pragma unroll
        for (int it = 0; it < 4; it++) {
            int idx = tid + it * 256;              // 0..1023 chunks of 16B
            int row = idx >> 3, c = idx & 7;
            cp16(sb_kv + row * 144 + c * 16, gQb + (size_t)row * D_ + c * 8);
        }
        CP_COMMIT(); CP_WAIT0();
        __syncthreads();
        __half* Qf = (__half*)smem;
#pragma unroll
        for (int ks = 0; ks < 4; ks++) {
            const __half* qb = Qtmp + (wq + g) * KST_H + ks * 16 + 2 * t;
            uint4 f;
            f.x = *(const uint32_t*)(qb);
            f.y = *(const uint32_t*)(qb + 8 * KST_H);
            f.z = *(const uint32_t*)(qb + 8);
            f.w = *(const uint32_t*)(qb + 8 * KST_H + 8);
            *(uint4*)((char*)Qf + wid * 2048 + ks * 512 + lane * 16) = f;
        }
        __syncthreads();
    }

    float m0r = -INFINITY, m1r = -INFINITY, l0 = 0.0f, l1 = 0.0f;
    float oacc[8][4];
#pragma unroll
    for (int nt = 0; nt < 8; nt++)
#pragma unroll
        for (int r = 0; r < 4; r++) oacc[nt][r] = 0.0f;

    const int* mrow0 = mask + ((size_t)bh * S_ + (qbase + wq + g)) * S_;
    const int* mrow1 = mrow0 + 8 * S_;

    // K/V tile staging: 4 cp16/thread (K: 64x64 f16; V: 64 d-rows x 64 keys)
#define STAGE_KV(tile)                                                        \
    do {                                                                      \
        uint32_t base = sb_kv + ((tile) & 1) * TILE_B;                        \
        int kb2 = (tile) * 64;                                                \
        int key0 = tid >> 3, c0 = tid & 7;                                    \
        cp16(base + key0 * 144 + c0 * 16,                                     \
             gKb + ((size_t)(kb2 + key0)) * D_ + c0 * 8);                     \
        cp16(base + (key0 + 32) * 144 + c0 * 16,                              \
             gKb + ((size_t)(kb2 + key0 + 32)) * D_ + c0 * 8);                \
        cp16(base + KS_BYTES2 + key0 * 144 + c0 * 16,                         \
             gVb + ((size_t)key0) * S_ + kb2 + c0 * 8);                       \
        cp16(base + KS_BYTES2 + (key0 + 32) * 144 + c0 * 16,                  \
             gVb + ((size_t)(key0 + 32)) * S_ + kb2 + c0 * 8);                \
    } while (0)

    STAGE_KV(0); CP_COMMIT();
    STAGE_KV(1); CP_COMMIT();

    for (int kt = 0; kt < 16; kt++) {
        const int kbase = kt * 64;
        const __half* Kf = (const __half*)(smem + 16384 + (kt & 1) * TILE_B);
        const __half* Vf = Kf + 64 * KST_H;

        // Mask: load + pack to one 32-bit word (bit nt*4+j gates sacc[nt][j])
        uint32_t mb = 0;
#pragma unroll
        for (int nt = 0; nt < 8; nt++) {
            int2 a = *(const int2*)&mrow0[kbase + nt * 8 + 2 * t];
            int2 b = *(const int2*)&mrow1[kbase + nt * 8 + 2 * t];
            mb |= (uint32_t)(a.x != 0) << (nt * 4 + 0);
            mb |= (uint32_t)(a.y != 0) << (nt * 4 + 1);
            mb |= (uint32_t)(b.x != 0) << (nt * 4 + 2);
            mb |= (uint32_t)(b.y != 0) << (nt * 4 + 3);
        }

        CP_WAIT1();            // tile kt complete (<=1 pending: kt+1)
        __syncthreads();

        // --- S = Q @ K^T : 4 k16 steps x 8 key-tiles ---
        float sacc[8][4];
#pragma unroll
        for (int nt = 0; nt < 8; nt++)
#pragma unroll
            for (int r = 0; r < 4; r++) sacc[nt][r] = 0.0f;
#pragma unroll
        for (int ks = 0; ks < 4; ks++) {
            uint4 qf = *(const uint4*)(smem + wid * 2048 + ks * 512 + lane * 16);
            uint32_t qa_[4] = { qf.x, qf.y, qf.z, qf.w };
#pragma unroll
            for (int nt = 0; nt < 8; nt++) {
                const __half* kb = Kf + (nt * 8 + g) * KST_H + ks * 16 + 2 * t;
                mma_f16(sacc[nt], qa_, *(const uint32_t*)kb,
                        *(const uint32_t*)(kb + 8));
            }
        }

        // --- Mask + exp2-scale softmax (f32) ---
        float rm0 = -INFINITY, rm1 = -INFINITY;
#pragma unroll
        for (int nt = 0; nt < 8; nt++) {
            sacc[nt][0] = ((mb >> (nt * 4 + 0)) & 1u) ? sacc[nt][0] * SCL : -INFINITY;
            sacc[nt][1] = ((mb >> (nt * 4 + 1)) & 1u) ? sacc[nt][1] * SCL : -INFINITY;
            sacc[nt][2] = ((mb >> (nt * 4 + 2)) & 1u) ? sacc[nt][2] * SCL : -INFINITY;
            sacc[nt][3] = ((mb >> (nt * 4 + 3)) & 1u) ? sacc[nt][3] * SCL : -INFINITY;
            rm0 = fmaxf(rm0, fmaxf(sacc[nt][0], sacc[nt][1]));
            rm1 = fmaxf(rm1, fmaxf(sacc[nt][2], sacc[nt][3]));
        }
#pragma unroll
        for (int off = 1; off <= 2; off <<= 1) {
            rm0 = fmaxf(rm0, __shfl_xor_sync(0xffffffffu, rm0, off));
            rm1 = fmaxf(rm1, __shfl_xor_sync(0xffffffffu, rm1, off));
        }
        float mn0 = fmaxf(m0r, rm0);
        float mn1 = fmaxf(m1r, rm1);
        float corr0 = (mn0 == -INFINITY) ? 1.0f : exp2f(m0r - mn0);
        float corr1 = (mn1 == -INFINITY) ? 1.0f : exp2f(m1r - mn1);
        m0r = mn0; m1r = mn1;

        float rs0 = 0.0f, rs1 = 0.0f;
#pragma unroll
        for (int nt = 0; nt < 8; nt++) {
            float p0 = (sacc[nt][0] == -INFINITY) ? 0.0f : exp2f(sacc[nt][0] - mn0);
            float p1 = (sacc[nt][1] == -INFINITY) ? 0.0f : exp2f(sacc[nt][1] - mn0);
            float p2 = (sacc[nt][2] == -INFINITY) ? 0.0f : exp2f(sacc[nt][2] - mn1);
            float p3 = (sacc[nt][3] == -INFINITY) ? 0.0f : exp2f(sacc[nt][3] - mn1);
            sacc[nt][0] = p0; sacc[nt][1] = p1;
            sacc[nt][2] = p2; sacc[nt][3] = p3;
            rs0 += p0 + p1;  rs1 += p2 + p3;
        }
#pragma unroll
        for (int off = 1; off <= 2; off <<= 1) {
            rs0 += __shfl_xor_sync(0xffffffffu, rs0, off);
            rs1 += __shfl_xor_sync(0xffffffffu, rs1, off);
        }
        l0 = l0 * corr0 + rs0;
        l1 = l1 * corr1 + rs1;
#pragma unroll
        for (int nt = 0; nt < 8; nt++) {
            oacc[nt][0] *= corr0; oacc[nt][1] *= corr0;
            oacc[nt][2] *= corr1; oacc[nt][3] *= corr1;
        }

        // --- O += P @ V : P A-frags = own-lane scores packed to half2 ---
#pragma unroll
        for (int ks = 0; ks < 4; ks++) {
            uint32_t pa_[4] = {
                packh2(sacc[2 * ks][0],     sacc[2 * ks][1]),
                packh2(sacc[2 * ks][2],     sacc[2 * ks][3]),
                packh2(sacc[2 * ks + 1][0], sacc[2 * ks + 1][1]),
                packh2(sacc[2 * ks + 1][2], sacc[2 * ks + 1][3])
            };
#pragma unroll
            for (int nt = 0; nt < 8; nt++) {
                const __half* vb = Vf + (nt * 8 + g) * KST_H + ks * 16 + 2 * t;
                mma_f16(oacc[nt], pa_, *(const uint32_t*)vb,
                        *(const uint32_t*)(vb + 8));
            }
        }
        __syncthreads();       // all warps done with buffer kt&1
        if (kt < 14) STAGE_KV(kt + 2);
        CP_COMMIT();
    }

    // --- Final normalize + write f32 [b*s][h*64+d] ---
    const int b = bh >> 4;
    const int h = bh & 15;
    const int r0 = qbase + wq + g;
    float inv0 = 1.0f / l0, inv1 = 1.0f / l1;
#pragma unroll
    for (int nt = 0; nt < 8; nt++) {
        int col = h * D_ + nt * 8 + 2 * t;
        float2 v0 = { oacc[nt][0] * inv0, oacc[nt][1] * inv0 };
        float2 v1 = { oacc[nt][2] * inv1, oacc[nt][3] * inv1 };
        *(float2*)(Og + ((size_t)(b * S_ + r0)) * (H_ * D_) + col)     = v0;
        *(float2*)(Og + ((size_t)(b * S_ + r0 + 8)) * (H_ * D_) + col) = v1;
    }
#undef STAGE_KV
}

// ---------------------------------------------------------------------------
// Launch
// ---------------------------------------------------------------------------
extern "C" void kernel_launch(void* const* d_in, const int* in_sizes, int n_in,
                              void* d_out, int out_size)
{
    const float* input  = (const float*)d_in[0];
    const float* latent = (const float*)d_in[1];
    const int*   mask   = (const int*)d_in[2];
    const float* Wq = (const float*)d_in[3];
    const float* bq = (const float*)d_in[4];
    const float* Wk = (const float*)d_in[5];
    const float* bk = (const float*)d_in[6];
    const float* Wv = (const float*)d_in[7];
    const float* bv = (const float*)d_in[8];
    const float* Wo = (const float*)d_in[9];
    const float* bo = (const float*)d_in[10];
    float* out = (float*)d_out;

    void *qp, *kp, *vp, *op;
    cudaGetSymbolAddress(&qp, g_Q);
    cudaGetSymbolAddress(&kp, g_K);
    cudaGetSymbolAddress(&vp, g_V);
    cudaGetSymbolAddress(&op, g_O);

    cudaFuncSetAttribute(gemm_mma<0>,
                         cudaFuncAttributeMaxDynamicSharedMemorySize, GEMM_SMEM);
    cudaFuncSetAttribute(gemm_mma<1>,
                         cudaFuncAttributeMaxDynamicSharedMemorySize, GEMM_SMEM);
    cudaFuncSetAttribute(gemm_mma<2>,
                         cudaFuncAttributeMaxDynamicSharedMemorySize, GEMM_SMEM);
    cudaFuncSetAttribute(attn_mma_kernel,
                         cudaFuncAttributeMaxDynamicSharedMemorySize, ATTN_SMEM);

    dim3 gg(LAT_ / 128, (B_ * S_) / 128);   // (8, 64)
    gemm_mma<1><<<gg, 256, GEMM_SMEM>>>(latent, Wq, bq, qp);
    gemm_mma<1><<<gg, 256, GEMM_SMEM>>>(input,  Wk, bk, kp);
    gemm_mma<2><<<gg, 256, GEMM_SMEM>>>(input,  Wv, bv, vp);

    dim3 ga(S_ / 128, B_ * H_);             // (8, 128)
    attn_mma_kernel<<<ga, 256, ATTN_SMEM>>>(mask, (float*)op);

    gemm_mma<0><<<gg, 256, GEMM_SMEM>>>((const float*)op, Wo, bo, out);
}

// round 16
// speedup vs baseline: 1.6764x; 1.4400x over previous
#include <cuda_runtime.h>
#include <cuda_fp16.h>
#include <math.h>
#include <stdint.h>

#define B_   8
#define S_   1024
#define H_   16
#define LAT_ 1024
#define D_   64

// ---------------------------------------------------------------------------
// Scratch (__device__ globals)
// ---------------------------------------------------------------------------
__device__ __half g_Q[(size_t)B_ * H_ * S_ * D_];     // [bh][s][d]
__device__ __half g_K[(size_t)B_ * H_ * S_ * D_];     // [bh][s][d]
__device__ __half g_V[(size_t)B_ * H_ * S_ * D_];     // [bh][d][s] transposed
__device__ __half g_O[(size_t)B_ * S_ * H_ * D_];     // [m][h*d] f16
__device__ __half g_Ah[(size_t)B_ * S_ * LAT_];       // latent f16
__device__ __half g_Bh[(size_t)B_ * S_ * LAT_];       // input f16
__device__ __half g_WT[4][(size_t)LAT_ * LAT_];       // weights [n][k] f16

// ---------------------------------------------------------------------------
// f16 m16n8k16 mma. g = lane>>2, t = lane&3.
//   A(16x16): a0=(g,2t:2t+1) a1=(g+8,2t:2t+1) a2=(g,2t+8:+9) a3=(g+8,2t+8:+9)
//   B(16x8):  b0=(2t:2t+1, g) b1=(2t+8:+9, g)
//   D(16x8):  d0=(g,2t) d1=(g,2t+1) d2=(g+8,2t) d3=(g+8,2t+1)
// ---------------------------------------------------------------------------
__device__ __forceinline__ void mma_f16(float* d, const uint32_t* a,
                                        uint32_t b0, uint32_t b1) {
    asm volatile(
        "mma.sync.aligned.m16n8k16.row.col.f32.f16.f16.f32 "
        "{%0,%1,%2,%3}, {%4,%5,%6,%7}, {%8,%9}, {%0,%1,%2,%3};"
        : "+f"(d[0]), "+f"(d[1]), "+f"(d[2]), "+f"(d[3])
        : "r"(a[0]), "r"(a[1]), "r"(a[2]), "r"(a[3]), "r"(b0), "r"(b1));
}
__device__ __forceinline__ uint32_t packh2(float lo, float hi) {
    __half2 h = __floats2half2_rn(lo, hi);
    return *(uint32_t*)&h;
}
__device__ __forceinline__ void cp16(uint32_t dst, const void* src) {
    asm volatile("cp.async.cg.shared.global [%0], [%1], 16;\n" :: "r"(dst), "l"(src));
}
#define CP_COMMIT() asm volatile("cp.async.commit_group;\n" ::: "memory")
#define CP_WAIT0()  asm volatile("cp.async.wait_group 0;\n" ::: "memory")
#define CP_WAIT1()  asm volatile("cp.async.wait_group 1;\n" ::: "memory")
#define CP_WAIT2()  asm volatile("cp.async.wait_group 2;\n" ::: "memory")

// ---------------------------------------------------------------------------
// Pre-pass kernels
// ---------------------------------------------------------------------------
__global__ __launch_bounds__(256)
void cvt_f16_kernel(const float* __restrict__ src, __half* __restrict__ dst)
{
    int i = (blockIdx.x * 256 + threadIdx.x) * 8;
    float4 v0 = *(const float4*)(src + i);
    float4 v1 = *(const float4*)(src + i + 4);
    uint4 o;
    o.x = packh2(v0.x, v0.y);  o.y = packh2(v0.z, v0.w);
    o.z = packh2(v1.x, v1.y);  o.w = packh2(v1.z, v1.w);
    *(uint4*)(dst + i) = o;
}

// dst[n][k] (f16) = src[k][n] (f32), 1024x1024
__global__ __launch_bounds__(256)
void transpose_cvt_kernel(const float* __restrict__ src, __half* __restrict__ dst)
{
    __shared__ float tle[32][33];
    int tx = threadIdx.x, ty = threadIdx.y;
    int x  = blockIdx.x * 32 + tx;
    int y0 = blockIdx.y * 32 + ty;
#pragma unroll
    for (int i = 0; i < 32; i += 8)
        tle[ty + i][tx] = src[(size_t)(y0 + i) * LAT_ + x];
    __syncthreads();
    int x2 = blockIdx.y * 32 + tx;
    int y2 = blockIdx.x * 32 + ty;
#pragma unroll
    for (int i = 0; i < 32; i += 8)
        dst[(size_t)(y2 + i) * LAT_ + x2] = __float2half_rn(tle[tx][ty + i]);
}

// ---------------------------------------------------------------------------
// fp16 tensor-core GEMM: C = A[M,1024](f16) @ Wt^T + bias  (Wt: [n][k] f16)
// Tile 128x128, BK=32 (2 k16 steps), cp.async 4-stage pipeline.
// Smem rows: 32 f16 + pad -> 40 halves (80B); fragment LDS.32 word pattern
// 20g+t, bijective mod 32 => conflict-free.
// OUT: 0 = f32 [m][n]; 1 = f16 [bh][s][d]; 2 = f16 [bh][d][s] (V transposed).
// ---------------------------------------------------------------------------
#define ASTH 40
#define TILE_H_BYTES (128 * ASTH * 2)            /* 10240 */
#define STAGE_H      (2 * TILE_H_BYTES)          /* 20480: A then B */
#define GEMM_SMEM    (4 * STAGE_H)               /* 81920 */

template <int OUT>
__global__ __launch_bounds__(256, 2)
void gemm_f16(const __half* __restrict__ A, const __half* __restrict__ Wt,
              const float* __restrict__ bias, void* __restrict__ Cp)
{
    extern __shared__ __align__(16) char gsm[];

    const int tid  = threadIdx.x;
    const int lane = tid & 31;
    const int wid  = tid >> 5;
    const int g = lane >> 2, t = lane & 3;
    const int wm = (wid & 1) * 64;
    const int wn = (wid >> 1) * 32;
    const int m0 = blockIdx.y * 128;
    const int n0 = blockIdx.x * 128;

    // Staging: A/B each 128 rows x 64B = 512 chunks; 2 A + 2 B per thread.
    const int row0 = tid >> 2, c0 = tid & 3;           // chunk 0
    const int row1 = (tid + 256) >> 2;                 // chunk 1 (c same)
    const __half* gA0 = A  + (size_t)(m0 + row0) * LAT_ + c0 * 8;
    const __half* gA1 = A  + (size_t)(m0 + row1) * LAT_ + c0 * 8;
    const __half* gB0 = Wt + (size_t)(n0 + row0) * LAT_ + c0 * 8;
    const __half* gB1 = Wt + (size_t)(n0 + row1) * LAT_ + c0 * 8;
    const uint32_t sbase = (uint32_t)__cvta_generic_to_shared(gsm);
    const uint32_t dA0 = row0 * 80 + c0 * 16;
    const uint32_t dA1 = row1 * 80 + c0 * 16;
    const uint32_t dB0 = TILE_H_BYTES + dA0;
    const uint32_t dB1 = TILE_H_BYTES + dA1;

    float acc[4][4][4];
#pragma unroll
    for (int i = 0; i < 4; i++)
#pragma unroll
        for (int j = 0; j < 4; j++)
#pragma unroll
            for (int r = 0; r < 4; r++) acc[i][j][r] = 0.0f;

#pragma unroll
    for (int s = 0; s < 3; s++) {
        uint32_t buf = sbase + s * STAGE_H;
        cp16(buf + dA0, gA0 + s * 32);
        cp16(buf + dA1, gA1 + s * 32);
        cp16(buf + dB0, gB0 + s * 32);
        cp16(buf + dB1, gB1 + s * 32);
        CP_COMMIT();
    }

    for (int kt = 0; kt < 32; kt++) {
        CP_WAIT2();
        __syncthreads();
        if (kt + 3 < 32) {
            uint32_t buf = sbase + ((kt + 3) & 3) * STAGE_H;
            cp16(buf + dA0, gA0 + (kt + 3) * 32);
            cp16(buf + dA1, gA1 + (kt + 3) * 32);
            cp16(buf + dB0, gB0 + (kt + 3) * 32);
            cp16(buf + dB1, gB1 + (kt + 3) * 32);
        }
        CP_COMMIT();

        const __half* As = (const __half*)(gsm + (size_t)(kt & 3) * STAGE_H);
        const __half* Bs = (const __half*)(gsm + (size_t)(kt & 3) * STAGE_H + TILE_H_BYTES);
#pragma unroll
        for (int ks = 0; ks < 2; ks++) {
            uint32_t a[4][4], b[4][2];
#pragma unroll
            for (int i = 0; i < 4; i++) {
                const __half* ab = As + (wm + i * 16 + g) * ASTH + ks * 16 + 2 * t;
                a[i][0] = *(const uint32_t*)(ab);
                a[i][1] = *(const uint32_t*)(ab + 8 * ASTH);
                a[i][2] = *(const uint32_t*)(ab + 8);
                a[i][3] = *(const uint32_t*)(ab + 8 * ASTH + 8);
            }
#pragma unroll
            for (int j = 0; j < 4; j++) {
                const __half* bb = Bs + (wn + j * 8 + g) * ASTH + ks * 16 + 2 * t;
                b[j][0] = *(const uint32_t*)(bb);
                b[j][1] = *(const uint32_t*)(bb + 8);
            }
#pragma unroll
            for (int i = 0; i < 4; i++)
#pragma unroll
                for (int j = 0; j < 4; j++)
                    mma_f16(acc[i][j], a[i], b[j][0], b[j][1]);
        }
    }

#pragma unroll
    for (int i = 0; i < 4; i++) {
        int r0 = m0 + wm + i * 16 + g;
#pragma unroll
        for (int j = 0; j < 4; j++) {
            int n = n0 + wn + j * 8 + 2 * t;
            float2 bb = *(const float2*)&bias[n];
            float2 v0 = { acc[i][j][0] + bb.x, acc[i][j][1] + bb.y };
            float2 v1 = { acc[i][j][2] + bb.x, acc[i][j][3] + bb.y };
            int bi = r0 >> 10, s = r0 & 1023;
            int h = n >> 6, d = n & 63;
            if (OUT == 0) {
                float* C = (float*)Cp;
                *(float2*)(C + (size_t)r0 * LAT_ + n)       = v0;
                *(float2*)(C + (size_t)(r0 + 8) * LAT_ + n) = v1;
            } else if (OUT == 1) {
                __half* C = (__half*)Cp;
                size_t base = (((size_t)(bi * H_ + h)) * S_ + s) * D_ + d;
                *(uint32_t*)&C[base]          = packh2(v0.x, v0.y);
                *(uint32_t*)&C[base + 8 * D_] = packh2(v1.x, v1.y);
            } else {
                __half* C = (__half*)Cp;   // [bh][d][s]
                size_t base = ((size_t)(bi * H_ + h) * D_ + d) * S_ + s;
                C[base]           = __float2half_rn(v0.x);
                C[base + S_]      = __float2half_rn(v0.y);
                C[base + 8]       = __float2half_rn(v1.x);
                C[base + S_ + 8]  = __float2half_rn(v1.y);
            }
        }
    }
}

// ---------------------------------------------------------------------------
// fp16 flash attention (round-15 version, unchanged except f16 output).
// ---------------------------------------------------------------------------
#define KST_H     72
#define KS_BYTES2 (64 * KST_H * 2)          /* 9216  */
#define TILE_B    (2 * KS_BYTES2)           /* 18432 */
#define ATTN_SMEM (16384 + 2 * TILE_B)      /* 53248 */
#define SCL 0.1803368801111244f             /* 0.125 * log2(e) */

__global__ __launch_bounds__(256, 2)
void attn_mma_kernel(const int* __restrict__ mask, __half* __restrict__ Og)
{
    extern __shared__ __align__(16) char smem[];
    const uint32_t sb    = (uint32_t)__cvta_generic_to_shared(smem);
    const uint32_t sb_kv = sb + 16384;

    const int tid  = threadIdx.x;
    const int lane = tid & 31;
    const int wid  = tid >> 5;
    const int g = lane >> 2, t = lane & 3;
    const int qbase = blockIdx.x * 128;
    const int bh    = blockIdx.y;
    const int wq    = wid * 16;

    const __half* gKb = g_K + (size_t)bh * S_ * D_;
    const __half* gVb = g_V + (size_t)bh * D_ * S_;

    // --- Stage Q (raw f16) -> transient -> fragment-major Qf ---
    {
        const __half* gQb = g_Q + ((size_t)bh * S_ + qbase) * D_;
        __half* Qtmp = (__half*)(smem + 16384);
#pragma unroll
        for (int it = 0; it < 4; it++) {
            int idx = tid + it * 256;
            int row = idx >> 3, c = idx & 7;
            cp16(sb_kv + row * 144 + c * 16, gQb + (size_t)row * D_ + c * 8);
        }
        CP_COMMIT(); CP_WAIT0();
        __syncthreads();
        __half* Qf = (__half*)smem;
#pragma unroll
        for (int ks = 0; ks < 4; ks++) {
            const __half* qb = Qtmp + (wq + g) * KST_H + ks * 16 + 2 * t;
            uint4 f;
            f.x = *(const uint32_t*)(qb);
            f.y = *(const uint32_t*)(qb + 8 * KST_H);
            f.z = *(const uint32_t*)(qb + 8);
            f.w = *(const uint32_t*)(qb + 8 * KST_H + 8);
            *(uint4*)((char*)Qf + wid * 2048 + ks * 512 + lane * 16) = f;
        }
        __syncthreads();
    }

    float m0r = -INFINITY, m1r = -INFINITY, l0 = 0.0f, l1 = 0.0f;
    float oacc[8][4];
#pragma unroll
    for (int nt = 0; nt < 8; nt++)
#pragma unroll
        for (int r = 0; r < 4; r++) oacc[nt][r] = 0.0f;

    const int* mrow0 = mask + ((size_t)bh * S_ + (qbase + wq + g)) * S_;
    const int* mrow1 = mrow0 + 8 * S_;

#define STAGE_KV(tile)                                                        \
    do {                                                                      \
        uint32_t base = sb_kv + ((tile) & 1) * TILE_B;                        \
        int kb2 = (tile) * 64;                                                \
        int key0 = tid >> 3, c0 = tid & 7;                                    \
        cp16(base + key0 * 144 + c0 * 16,                                     \
             gKb + ((size_t)(kb2 + key0)) * D_ + c0 * 8);                     \
        cp16(base + (key0 + 32) * 144 + c0 * 16,                              \
             gKb + ((size_t)(kb2 + key0 + 32)) * D_ + c0 * 8);                \
        cp16(base + KS_BYTES2 + key0 * 144 + c0 * 16,                         \
             gVb + ((size_t)key0) * S_ + kb2 + c0 * 8);                       \
        cp16(base + KS_BYTES2 + (key0 + 32) * 144 + c0 * 16,                  \
             gVb + ((size_t)(key0 + 32)) * S_ + kb2 + c0 * 8);                \
    } while (0)

    STAGE_KV(0); CP_COMMIT();
    STAGE_KV(1); CP_COMMIT();

    for (int kt = 0; kt < 16; kt++) {
        const int kbase = kt * 64;
        const __half* Kf = (const __half*)(smem + 16384 + (kt & 1) * TILE_B);
        const __half* Vf = Kf + 64 * KST_H;

        uint32_t mb = 0;
#pragma unroll
        for (int nt = 0; nt < 8; nt++) {
            int2 a = *(const int2*)&mrow0[kbase + nt * 8 + 2 * t];
            int2 b = *(const int2*)&mrow1[kbase + nt * 8 + 2 * t];
            mb |= (uint32_t)(a.x != 0) << (nt * 4 + 0);
            mb |= (uint32_t)(a.y != 0) << (nt * 4 + 1);
            mb |= (uint32_t)(b.x != 0) << (nt * 4 + 2);
            mb |= (uint32_t)(b.y != 0) << (nt * 4 + 3);
        }

        CP_WAIT1();
        __syncthreads();

        float sacc[8][4];
#pragma unroll
        for (int nt = 0; nt < 8; nt++)
#pragma unroll
            for (int r = 0; r < 4; r++) sacc[nt][r] = 0.0f;
#pragma unroll
        for (int ks = 0; ks < 4; ks++) {
            uint4 qf = *(const uint4*)(smem + wid * 2048 + ks * 512 + lane * 16);
            uint32_t qa_[4] = { qf.x, qf.y, qf.z, qf.w };
#pragma unroll
            for (int nt = 0; nt < 8; nt++) {
                const __half* kb = Kf + (nt * 8 + g) * KST_H + ks * 16 + 2 * t;
                mma_f16(sacc[nt], qa_, *(const uint32_t*)kb,
                        *(const uint32_t*)(kb + 8));
            }
        }

        float rm0 = -INFINITY, rm1 = -INFINITY;
#pragma unroll
        for (int nt = 0; nt < 8; nt++) {
            sacc[nt][0] = ((mb >> (nt * 4 + 0)) & 1u) ? sacc[nt][0] * SCL : -INFINITY;
            sacc[nt][1] = ((mb >> (nt * 4 + 1)) & 1u) ? sacc[nt][1] * SCL : -INFINITY;
            sacc[nt][2] = ((mb >> (nt * 4 + 2)) & 1u) ? sacc[nt][2] * SCL : -INFINITY;
            sacc[nt][3] = ((mb >> (nt * 4 + 3)) & 1u) ? sacc[nt][3] * SCL : -INFINITY;
            rm0 = fmaxf(rm0, fmaxf(sacc[nt][0], sacc[nt][1]));
            rm1 = fmaxf(rm1, fmaxf(sacc[nt][2], sacc[nt][3]));
        }
#pragma unroll
        for (int off = 1; off <= 2; off <<= 1) {
            rm0 = fmaxf(rm0, __shfl_xor_sync(0xffffffffu, rm0, off));
            rm1 = fmaxf(rm1, __shfl_xor_sync(0xffffffffu, rm1, off));
        }
        float mn0 = fmaxf(m0r, rm0);
        float mn1 = fmaxf(m1r, rm1);
        float corr0 = (mn0 == -INFINITY) ? 1.0f : exp2f(m0r - mn0);
        float corr1 = (mn1 == -INFINITY) ? 1.0f : exp2f(m1r - mn1);
        m0r = mn0; m1r = mn1;

        float rs0 = 0.0f, rs1 = 0.0f;
#pragma unroll
        for (int nt = 0; nt < 8; nt++) {
            float p0 = (sacc[nt][0] == -INFINITY) ? 0.0f : exp2f(sacc[nt][0] - mn0);
            float p1 = (sacc[nt][1] == -INFINITY) ? 0.0f : exp2f(sacc[nt][1] - mn0);
            float p2 = (sacc[nt][2] == -INFINITY) ? 0.0f : exp2f(sacc[nt][2] - mn1);
            float p3 = (sacc[nt][3] == -INFINITY) ? 0.0f : exp2f(sacc[nt][3] - mn1);
            sacc[nt][0] = p0; sacc[nt][1] = p1;
            sacc[nt][2] = p2; sacc[nt][3] = p3;
            rs0 += p0 + p1;  rs1 += p2 + p3;
        }
#pragma unroll
        for (int off = 1; off <= 2; off <<= 1) {
            rs0 += __shfl_xor_sync(0xffffffffu, rs0, off);
            rs1 += __shfl_xor_sync(0xffffffffu, rs1, off);
        }
        l0 = l0 * corr0 + rs0;
        l1 = l1 * corr1 + rs1;
#pragma unroll
        for (int nt = 0; nt < 8; nt++) {
            oacc[nt][0] *= corr0; oacc[nt][1] *= corr0;
            oacc[nt][2] *= corr1; oacc[nt][3] *= corr1;
        }

#pragma unroll
        for (int ks = 0; ks < 4; ks++) {
            uint32_t pa_[4] = {
                packh2(sacc[2 * ks][0],     sacc[2 * ks][1]),
                packh2(sacc[2 * ks][2],     sacc[2 * ks][3]),
                packh2(sacc[2 * ks + 1][0], sacc[2 * ks + 1][1]),
                packh2(sacc[2 * ks + 1][2], sacc[2 * ks + 1][3])
            };
#pragma unroll
            for (int nt = 0; nt < 8; nt++) {
                const __half* vb = Vf + (nt * 8 + g) * KST_H + ks * 16 + 2 * t;
                mma_f16(oacc[nt], pa_, *(const uint32_t*)vb,
                        *(const uint32_t*)(vb + 8));
            }
        }
        __syncthreads();
        if (kt < 14) STAGE_KV(kt + 2);
        CP_COMMIT();
    }

    // --- Final normalize + write f16 [b*s][h*64+d] ---
    const int b = bh >> 4;
    const int h = bh & 15;
    const int r0 = qbase + wq + g;
    float inv0 = 1.0f / l0, inv1 = 1.0f / l1;
#pragma unroll
    for (int nt = 0; nt < 8; nt++) {
        int col = h * D_ + nt * 8 + 2 * t;
        *(uint32_t*)(Og + ((size_t)(b * S_ + r0)) * (H_ * D_) + col) =
            packh2(oacc[nt][0] * inv0, oacc[nt][1] * inv0);
        *(uint32_t*)(Og + ((size_t)(b * S_ + r0 + 8)) * (H_ * D_) + col) =
            packh2(oacc[nt][2] * inv1, oacc[nt][3] * inv1);
    }
#undef STAGE_KV
}

// ---------------------------------------------------------------------------
// Launch
// ---------------------------------------------------------------------------
extern "C" void kernel_launch(void* const* d_in, const int* in_sizes, int n_in,
                              void* d_out, int out_size)
{
    const float* input  = (const float*)d_in[0];
    const float* latent = (const float*)d_in[1];
    const int*   mask   = (const int*)d_in[2];
    const float* Wq = (const float*)d_in[3];
    const float* bq = (const float*)d_in[4];
    const float* Wk = (const float*)d_in[5];
    const float* bk = (const float*)d_in[6];
    const float* Wv = (const float*)d_in[7];
    const float* bv = (const float*)d_in[8];
    const float* Wo = (const float*)d_in[9];
    const float* bo = (const float*)d_in[10];
    float* out = (float*)d_out;

    void *qp, *kp, *vp, *op, *ah, *bhp, *wt;
    cudaGetSymbolAddress(&qp, g_Q);
    cudaGetSymbolAddress(&kp, g_K);
    cudaGetSymbolAddress(&vp, g_V);
    cudaGetSymbolAddress(&op, g_O);
    cudaGetSymbolAddress(&ah, g_Ah);
    cudaGetSymbolAddress(&bhp, g_Bh);
    cudaGetSymbolAddress(&wt, g_WT);
    __half* wqT = (__half*)wt + 0 * (size_t)LAT_ * LAT_;
    __half* wkT = (__half*)wt + 1 * (size_t)LAT_ * LAT_;
    __half* wvT = (__half*)wt + 2 * (size_t)LAT_ * LAT_;
    __half* woT = (__half*)wt + 3 * (size_t)LAT_ * LAT_;

    cudaFuncSetAttribute(gemm_f16<0>,
                         cudaFuncAttributeMaxDynamicSharedMemorySize, GEMM_SMEM);
    cudaFuncSetAttribute(gemm_f16<1>,
                         cudaFuncAttributeMaxDynamicSharedMemorySize, GEMM_SMEM);
    cudaFuncSetAttribute(gemm_f16<2>,
                         cudaFuncAttributeMaxDynamicSharedMemorySize, GEMM_SMEM);
    cudaFuncSetAttribute(attn_mma_kernel,
                         cudaFuncAttributeMaxDynamicSharedMemorySize, ATTN_SMEM);

    // Pre-pass: convert activations, transpose+convert weights
    const int nact = B_ * S_ * LAT_;               // 8M elements
    cvt_f16_kernel<<<nact / (256 * 8), 256>>>(latent, (__half*)ah);
    cvt_f16_kernel<<<nact / (256 * 8), 256>>>(input,  (__half*)bhp);
    dim3 tb(32, 8), tg(32, 32);
    transpose_cvt_kernel<<<tg, tb>>>(Wq, wqT);
    transpose_cvt_kernel<<<tg, tb>>>(Wk, wkT);
    transpose_cvt_kernel<<<tg, tb>>>(Wv, wvT);
    transpose_cvt_kernel<<<tg, tb>>>(Wo, woT);

    // fp16 GEMMs
    dim3 gg(LAT_ / 128, (B_ * S_) / 128);   // (8, 64)
    gemm_f16<1><<<gg, 256, GEMM_SMEM>>>((const __half*)ah,  wqT, bq, qp);
    gemm_f16<1><<<gg, 256, GEMM_SMEM>>>((const __half*)bhp, wkT, bk, kp);
    gemm_f16<2><<<gg, 256, GEMM_SMEM>>>((const __half*)bhp, wvT, bv, vp);

    dim3 ga(S_ / 128, B_ * H_);             // (8, 128)
    attn_mma_kernel<<<ga, 256, ATTN_SMEM>>>(mask, (__half*)op);

    gemm_f16<0><<<gg, 256, GEMM_SMEM>>>((const __half*)op, woT, bo, out);
}

// round 17
// speedup vs baseline: 1.8572x; 1.1078x over previous
#include <cuda_runtime.h>
#include <cuda_fp16.h>
#include <math.h>
#include <stdint.h>

#define B_   8
#define S_   1024
#define H_   16
#define LAT_ 1024
#define D_   64

// ---------------------------------------------------------------------------
// Scratch (__device__ globals)
// ---------------------------------------------------------------------------
__device__ __half g_Q[(size_t)B_ * H_ * S_ * D_];     // [bh][s][d]
__device__ __half g_K[(size_t)B_ * H_ * S_ * D_];     // [bh][s][d]
__device__ __half g_V[(size_t)B_ * H_ * S_ * D_];     // [bh][d][s] transposed
__device__ __half g_O[(size_t)B_ * S_ * H_ * D_];     // [m][h*d] f16
__device__ __half g_Ah[(size_t)B_ * S_ * LAT_];       // latent f16
__device__ __half g_Bh[(size_t)B_ * S_ * LAT_];       // input f16
__device__ __half g_WT[4][(size_t)LAT_ * LAT_];       // weights [n][k] f16

// ---------------------------------------------------------------------------
// f16 m16n8k16 mma + ldmatrix. g = lane>>2, t = lane&3.
//   A: a0=(g,2t:2t+1) a1=(g+8,..) a2=(g,2t+8:+9) a3=(g+8,2t+8:+9)
//   B: b0=(2t:2t+1,g) b1=(2t+8:+9,g); D: d0=(g,2t) d1=(g,2t+1) d2/d3 +8row
// ldmatrix.x4: lane l supplies row (l&7) of matrix (l>>3); result r_m is
// matrix m with lane(g,t) holding element pair (row g, cols 2t:2t+1).
// ---------------------------------------------------------------------------
__device__ __forceinline__ void mma_f16(float* d, const uint32_t* a,
                                        uint32_t b0, uint32_t b1) {
    asm volatile(
        "mma.sync.aligned.m16n8k16.row.col.f32.f16.f16.f32 "
        "{%0,%1,%2,%3}, {%4,%5,%6,%7}, {%8,%9}, {%0,%1,%2,%3};"
        : "+f"(d[0]), "+f"(d[1]), "+f"(d[2]), "+f"(d[3])
        : "r"(a[0]), "r"(a[1]), "r"(a[2]), "r"(a[3]), "r"(b0), "r"(b1));
}
__device__ __forceinline__ void ldsm4(uint32_t* r, uint32_t saddr) {
    asm volatile(
        "ldmatrix.sync.aligned.m8n8.x4.shared.b16 {%0,%1,%2,%3}, [%4];"
        : "=r"(r[0]), "=r"(r[1]), "=r"(r[2]), "=r"(r[3]) : "r"(saddr));
}
__device__ __forceinline__ uint32_t packh2(float lo, float hi) {
    __half2 h = __floats2half2_rn(lo, hi);
    return *(uint32_t*)&h;
}
__device__ __forceinline__ void cp16(uint32_t dst, const void* src) {
    asm volatile("cp.async.cg.shared.global [%0], [%1], 16;\n" :: "r"(dst), "l"(src));
}
#define CP_COMMIT() asm volatile("cp.async.commit_group;\n" ::: "memory")
#define CP_WAIT0()  asm volatile("cp.async.wait_group 0;\n" ::: "memory")
#define CP_WAIT1()  asm volatile("cp.async.wait_group 1;\n" ::: "memory")
#define CP_WAIT2()  asm volatile("cp.async.wait_group 2;\n" ::: "memory")

// ---------------------------------------------------------------------------
// Pre-pass kernels
// ---------------------------------------------------------------------------
__global__ __launch_bounds__(256)
void cvt_f16_kernel(const float* __restrict__ src, __half* __restrict__ dst)
{
    int i = (blockIdx.x * 256 + threadIdx.x) * 8;
    float4 v0 = *(const float4*)(src + i);
    float4 v1 = *(const float4*)(src + i + 4);
    uint4 o;
    o.x = packh2(v0.x, v0.y);  o.y = packh2(v0.z, v0.w);
    o.z = packh2(v1.x, v1.y);  o.w = packh2(v1.z, v1.w);
    *(uint4*)(dst + i) = o;
}

__global__ __launch_bounds__(256)
void transpose_cvt_kernel(const float* __restrict__ src, __half* __restrict__ dst)
{
    __shared__ float tle[32][33];
    int tx = threadIdx.x, ty = threadIdx.y;
    int x  = blockIdx.x * 32 + tx;
    int y0 = blockIdx.y * 32 + ty;
#pragma unroll
    for (int i = 0; i < 32; i += 8)
        tle[ty + i][tx] = src[(size_t)(y0 + i) * LAT_ + x];
    __syncthreads();
    int x2 = blockIdx.y * 32 + tx;
    int y2 = blockIdx.x * 32 + ty;
#pragma unroll
    for (int i = 0; i < 32; i += 8)
        dst[(size_t)(y2 + i) * LAT_ + x2] = __float2half_rn(tle[tx][ty + i]);
}

// ---------------------------------------------------------------------------
// fp16 GEMM with LDSM fragment feeds: C = A(f16) @ Wt^T + bias (Wt [n][k] f16)
// Tile 128x128, BK=32, cp.async 4-stage. Rows 40 halves (80B = 20 words:
// LDSM 8-row phases hit all 32 banks once — conflict-free).
// OUT: 0 = f32 [m][n]; 1 = f16 [bh][s][d]; 2 = f16 [bh][d][s] (V transposed).
// ---------------------------------------------------------------------------
#define ASTH 40
#define TILE_H_BYTES (128 * ASTH * 2)            /* 10240 */
#define STAGE_H      (2 * TILE_H_BYTES)          /* 20480 */
#define GEMM_SMEM    (4 * STAGE_H)               /* 81920 */

template <int OUT>
__global__ __launch_bounds__(256, 2)
void gemm_f16(const __half* __restrict__ A, const __half* __restrict__ Wt,
              const float* __restrict__ bias, void* __restrict__ Cp)
{
    extern __shared__ __align__(16) char gsm[];

    const int tid  = threadIdx.x;
    const int lane = tid & 31;
    const int wid  = tid >> 5;
    const int g = lane >> 2, t = lane & 3;
    const int wm = (wid & 1) * 64;
    const int wn = (wid >> 1) * 32;
    const int m0 = blockIdx.y * 128;
    const int n0 = blockIdx.x * 128;

    const int row0 = tid >> 2, c0 = tid & 3;
    const int row1 = (tid + 256) >> 2;
    const __half* gA0 = A  + (size_t)(m0 + row0) * LAT_ + c0 * 8;
    const __half* gA1 = A  + (size_t)(m0 + row1) * LAT_ + c0 * 8;
    const __half* gB0 = Wt + (size_t)(n0 + row0) * LAT_ + c0 * 8;
    const __half* gB1 = Wt + (size_t)(n0 + row1) * LAT_ + c0 * 8;
    const uint32_t sbase = (uint32_t)__cvta_generic_to_shared(gsm);
    const uint32_t dA0 = row0 * 80 + c0 * 16;
    const uint32_t dA1 = row1 * 80 + c0 * 16;
    const uint32_t dB0 = TILE_H_BYTES + dA0;
    const uint32_t dB1 = TILE_H_BYTES + dA1;

    // LDSM lane-address components
    const uint32_t aOff = (uint32_t)(wm + ((lane >> 3) & 1) * 8 + (lane & 7)) * 80
                        + (uint32_t)(lane >> 4) * 16;
    const uint32_t bOff = (uint32_t)(wn + (lane & 7)) * 80 + (uint32_t)(lane >> 3) * 16;

    float acc[4][4][4];
#pragma unroll
    for (int i = 0; i < 4; i++)
#pragma unroll
        for (int j = 0; j < 4; j++)
#pragma unroll
            for (int r = 0; r < 4; r++) acc[i][j][r] = 0.0f;

#pragma unroll
    for (int s = 0; s < 3; s++) {
        uint32_t buf = sbase + s * STAGE_H;
        cp16(buf + dA0, gA0 + s * 32);
        cp16(buf + dA1, gA1 + s * 32);
        cp16(buf + dB0, gB0 + s * 32);
        cp16(buf + dB1, gB1 + s * 32);
        CP_COMMIT();
    }

    for (int kt = 0; kt < 32; kt++) {
        CP_WAIT2();
        __syncthreads();
        if (kt + 3 < 32) {
            uint32_t buf = sbase + ((kt + 3) & 3) * STAGE_H;
            cp16(buf + dA0, gA0 + (kt + 3) * 32);
            cp16(buf + dA1, gA1 + (kt + 3) * 32);
            cp16(buf + dB0, gB0 + (kt + 3) * 32);
            cp16(buf + dB1, gB1 + (kt + 3) * 32);
        }
        CP_COMMIT();

        const uint32_t sA = sbase + (uint32_t)(kt & 3) * STAGE_H;
        const uint32_t sB = sA + TILE_H_BYTES;

        // B frags: one LDSM.x4 per j covers b0,b1 of BOTH ks steps
        uint32_t b[4][4];
#pragma unroll
        for (int j = 0; j < 4; j++)
            ldsm4(b[j], sB + j * 640 + bOff);

#pragma unroll
        for (int ks = 0; ks < 2; ks++) {
            uint32_t a[4][4];
#pragma unroll
            for (int i = 0; i < 4; i++)
                ldsm4(a[i], sA + i * 1280 + ks * 32 + aOff);
#pragma unroll
            for (int i = 0; i < 4; i++)
#pragma unroll
                for (int j = 0; j < 4; j++)
                    mma_f16(acc[i][j], a[i], b[j][2 * ks], b[j][2 * ks + 1]);
        }
    }

#pragma unroll
    for (int i = 0; i < 4; i++) {
        int r0 = m0 + wm + i * 16 + g;
#pragma unroll
        for (int j = 0; j < 4; j++) {
            int n = n0 + wn + j * 8 + 2 * t;
            float2 bb = *(const float2*)&bias[n];
            float2 v0 = { acc[i][j][0] + bb.x, acc[i][j][1] + bb.y };
            float2 v1 = { acc[i][j][2] + bb.x, acc[i][j][3] + bb.y };
            int bi = r0 >> 10, s = r0 & 1023;
            int h = n >> 6, d = n & 63;
            if (OUT == 0) {
                float* C = (float*)Cp;
                *(float2*)(C + (size_t)r0 * LAT_ + n)       = v0;
                *(float2*)(C + (size_t)(r0 + 8) * LAT_ + n) = v1;
            } else if (OUT == 1) {
                __half* C = (__half*)Cp;
                size_t base = (((size_t)(bi * H_ + h)) * S_ + s) * D_ + d;
                *(uint32_t*)&C[base]          = packh2(v0.x, v0.y);
                *(uint32_t*)&C[base + 8 * D_] = packh2(v1.x, v1.y);
            } else {
                __half* C = (__half*)Cp;   // [bh][d][s]
                size_t base = ((size_t)(bi * H_ + h) * D_ + d) * S_ + s;
                C[base]           = __float2half_rn(v0.x);
                C[base + S_]      = __float2half_rn(v0.y);
                C[base + 8]       = __float2half_rn(v1.x);
                C[base + S_ + 8]  = __float2half_rn(v1.y);
            }
        }
    }
}

// ---------------------------------------------------------------------------
// fp16 flash attention with LDSM K/V fragment feeds.
// 128 q/block, 8 warps, 2 CTAs/SM. Q A-frags in regs for the whole kernel.
// K/V rows 144B = 36 words: LDSM phases hit all 32 banks once (conflict-free).
// ---------------------------------------------------------------------------
#define KST_H     72
#define KS_BYTES2 (64 * KST_H * 2)          /* 9216  */
#define TILE_B    (2 * KS_BYTES2)           /* 18432 */
#define ATTN_SMEM (16384 + 2 * TILE_B)      /* 53248 */
#define SCL 0.1803368801111244f             /* 0.125 * log2(e) */

__global__ __launch_bounds__(256, 2)
void attn_mma_kernel(const int* __restrict__ mask, __half* __restrict__ Og)
{
    extern __shared__ __align__(16) char smem[];
    const uint32_t sb    = (uint32_t)__cvta_generic_to_shared(smem);
    const uint32_t sb_kv = sb + 16384;

    const int tid  = threadIdx.x;
    const int lane = tid & 31;
    const int wid  = tid >> 5;
    const int g = lane >> 2, t = lane & 3;
    const int qbase = blockIdx.x * 128;
    const int bh    = blockIdx.y;
    const int wq    = wid * 16;

    const __half* gKb = g_K + (size_t)bh * S_ * D_;
    const __half* gVb = g_V + (size_t)bh * D_ * S_;

    // LDSM lane-address component for K/V (matrix m = lane>>3):
    // row = (lane&7), col bytes = (m>>1)*32 + (m&1)*16  [+ kspair*64]
    const uint32_t kvOff = (uint32_t)(lane & 7) * 144
                         + (uint32_t)(lane >> 4) * 32
                         + (uint32_t)((lane >> 3) & 1) * 16;

    // --- Stage Q (raw f16) -> transient -> fragment-major -> registers ---
    uint32_t qa[4][4];
    {
        const __half* gQb = g_Q + ((size_t)bh * S_ + qbase) * D_;
        __half* Qtmp = (__half*)(smem + 16384);
#pragma unroll
        for (int it = 0; it < 4; it++) {
            int idx = tid + it * 256;
            int row = idx >> 3, c = idx & 7;
            cp16(sb_kv + row * 144 + c * 16, gQb + (size_t)row * D_ + c * 8);
        }
        CP_COMMIT(); CP_WAIT0();
        __syncthreads();
        // ldmatrix straight out of the row-major transient (A-frag per ks)
        const uint32_t qOff = (uint32_t)(wq + ((lane >> 3) & 1) * 8 + (lane & 7)) * 144
                            + (uint32_t)(lane >> 4) * 16;
#pragma unroll
        for (int ks = 0; ks < 4; ks++)
            ldsm4(qa[ks], sb_kv + ks * 32 + qOff);
        __syncthreads();   // everyone done reading Qtmp; K/V staging may begin
    }

    float m0r = -INFINITY, m1r = -INFINITY, l0 = 0.0f, l1 = 0.0f;
    float oacc[8][4];
#pragma unroll
    for (int nt = 0; nt < 8; nt++)
#pragma unroll
        for (int r = 0; r < 4; r++) oacc[nt][r] = 0.0f;

    const int* mrow0 = mask + ((size_t)bh * S_ + (qbase + wq + g)) * S_;
    const int* mrow1 = mrow0 + 8 * S_;

#define STAGE_KV(tile)                                                        \
    do {                                                                      \
        uint32_t base = sb_kv + ((tile) & 1) * TILE_B;                        \
        int kb2 = (tile) * 64;                                                \
        int key0 = tid >> 3, c0 = tid & 7;                                    \
        cp16(base + key0 * 144 + c0 * 16,                                     \
             gKb + ((size_t)(kb2 + key0)) * D_ + c0 * 8);                     \
        cp16(base + (key0 + 32) * 144 + c0 * 16,                              \
             gKb + ((size_t)(kb2 + key0 + 32)) * D_ + c0 * 8);                \
        cp16(base + KS_BYTES2 + key0 * 144 + c0 * 16,                         \
             gVb + ((size_t)key0) * S_ + kb2 + c0 * 8);                       \
        cp16(base + KS_BYTES2 + (key0 + 32) * 144 + c0 * 16,                  \
             gVb + ((size_t)(key0 + 32)) * S_ + kb2 + c0 * 8);                \
    } while (0)

    STAGE_KV(0); CP_COMMIT();
    STAGE_KV(1); CP_COMMIT();

    for (int kt = 0; kt < 16; kt++) {
        const int kbase = kt * 64;
        const uint32_t sK = sb_kv + (uint32_t)(kt & 1) * TILE_B;
        const uint32_t sV = sK + KS_BYTES2;

        uint32_t mb = 0;
#pragma unroll
        for (int nt = 0; nt < 8; nt++) {
            int2 a = *(const int2*)&mrow0[kbase + nt * 8 + 2 * t];
            int2 b = *(const int2*)&mrow1[kbase + nt * 8 + 2 * t];
            mb |= (uint32_t)(a.x != 0) << (nt * 4 + 0);
            mb |= (uint32_t)(a.y != 0) << (nt * 4 + 1);
            mb |= (uint32_t)(b.x != 0) << (nt * 4 + 2);
            mb |= (uint32_t)(b.y != 0) << (nt * 4 + 3);
        }

        CP_WAIT1();
        __syncthreads();

        // --- S = Q @ K^T : per nt, 2 LDSM.x4 give b0,b1 for all 4 ks ---
        float sacc[8][4];
#pragma unroll
        for (int nt = 0; nt < 8; nt++) {
#pragma unroll
            for (int r = 0; r < 4; r++) sacc[nt][r] = 0.0f;
            uint32_t kf0[4], kf1[4];
            ldsm4(kf0, sK + nt * 1152 + kvOff);          // ks 0,1
            ldsm4(kf1, sK + nt * 1152 + 64 + kvOff);     // ks 2,3
            mma_f16(sacc[nt], qa[0], kf0[0], kf0[1]);
            mma_f16(sacc[nt], qa[1], kf0[2], kf0[3]);
            mma_f16(sacc[nt], qa[2], kf1[0], kf1[1]);
            mma_f16(sacc[nt], qa[3], kf1[2], kf1[3]);
        }

        // --- Mask + exp2-scale softmax (f32) ---
        float rm0 = -INFINITY, rm1 = -INFINITY;
#pragma unroll
        for (int nt = 0; nt < 8; nt++) {
            sacc[nt][0] = ((mb >> (nt * 4 + 0)) & 1u) ? sacc[nt][0] * SCL : -INFINITY;
            sacc[nt][1] = ((mb >> (nt * 4 + 1)) & 1u) ? sacc[nt][1] * SCL : -INFINITY;
            sacc[nt][2] = ((mb >> (nt * 4 + 2)) & 1u) ? sacc[nt][2] * SCL : -INFINITY;
            sacc[nt][3] = ((mb >> (nt * 4 + 3)) & 1u) ? sacc[nt][3] * SCL : -INFINITY;
            rm0 = fmaxf(rm0, fmaxf(sacc[nt][0], sacc[nt][1]));
            rm1 = fmaxf(rm1, fmaxf(sacc[nt][2], sacc[nt][3]));
        }
#pragma unroll
        for (int off = 1; off <= 2; off <<= 1) {
            rm0 = fmaxf(rm0, __shfl_xor_sync(0xffffffffu, rm0, off));
            rm1 = fmaxf(rm1, __shfl_xor_sync(0xffffffffu, rm1, off));
        }
        float mn0 = fmaxf(m0r, rm0);
        float mn1 = fmaxf(m1r, rm1);
        float corr0 = (mn0 == -INFINITY) ? 1.0f : exp2f(m0r - mn0);
        float corr1 = (mn1 == -INFINITY) ? 1.0f : exp2f(m1r - mn1);
        m0r = mn0; m1r = mn1;

        float rs0 = 0.0f, rs1 = 0.0f;
#pragma unroll
        for (int nt = 0; nt < 8; nt++) {
            float p0 = (sacc[nt][0] == -INFINITY) ? 0.0f : exp2f(sacc[nt][0] - mn0);
            float p1 = (sacc[nt][1] == -INFINITY) ? 0.0f : exp2f(sacc[nt][1] - mn0);
            float p2 = (sacc[nt][2] == -INFINITY) ? 0.0f : exp2f(sacc[nt][2] - mn1);
            float p3 = (sacc[nt][3] == -INFINITY) ? 0.0f : exp2f(sacc[nt][3] - mn1);
            sacc[nt][0] = p0; sacc[nt][1] = p1;
            sacc[nt][2] = p2; sacc[nt][3] = p3;
            rs0 += p0 + p1;  rs1 += p2 + p3;
        }
#pragma unroll
        for (int off = 1; off <= 2; off <<= 1) {
            rs0 += __shfl_xor_sync(0xffffffffu, rs0, off);
            rs1 += __shfl_xor_sync(0xffffffffu, rs1, off);
        }
        l0 = l0 * corr0 + rs0;
        l1 = l1 * corr1 + rs1;
#pragma unroll
        for (int nt = 0; nt < 8; nt++) {
            oacc[nt][0] *= corr0; oacc[nt][1] *= corr0;
            oacc[nt][2] *= corr1; oacc[nt][3] *= corr1;
        }

        // --- O += P @ V : build all 4 P A-frags, then per nt 2 LDSM + 4 MMA ---
        uint32_t pa[4][4];
#pragma unroll
        for (int ks = 0; ks < 4; ks++) {
            pa[ks][0] = packh2(sacc[2 * ks][0],     sacc[2 * ks][1]);
            pa[ks][1] = packh2(sacc[2 * ks][2],     sacc[2 * ks][3]);
            pa[ks][2] = packh2(sacc[2 * ks + 1][0], sacc[2 * ks + 1][1]);
            pa[ks][3] = packh2(sacc[2 * ks + 1][2], sacc[2 * ks + 1][3]);
        }
#pragma unroll
        for (int nt = 0; nt < 8; nt++) {
            uint32_t vf0[4], vf1[4];
            ldsm4(vf0, sV + nt * 1152 + kvOff);          // ks 0,1
            ldsm4(vf1, sV + nt * 1152 + 64 + kvOff);     // ks 2,3
            mma_f16(oacc[nt], pa[0], vf0[0], vf0[1]);
            mma_f16(oacc[nt], pa[1], vf0[2], vf0[3]);
            mma_f16(oacc[nt], pa[2], vf1[0], vf1[1]);
            mma_f16(oacc[nt], pa[3], vf1[2], vf1[3]);
        }
        __syncthreads();
        if (kt < 14) STAGE_KV(kt + 2);
        CP_COMMIT();
    }

    // --- Final normalize + write f16 [b*s][h*64+d] ---
    const int b = bh >> 4;
    const int h = bh & 15;
    const int r0 = qbase + wq + g;
    float inv0 = 1.0f / l0, inv1 = 1.0f / l1;
#pragma unroll
    for (int nt = 0; nt < 8; nt++) {
        int col = h * D_ + nt * 8 + 2 * t;
        *(uint32_t*)(Og + ((size_t)(b * S_ + r0)) * (H_ * D_) + col) =
            packh2(oacc[nt][0] * inv0, oacc[nt][1] * inv0);
        *(uint32_t*)(Og + ((size_t)(b * S_ + r0 + 8)) * (H_ * D_) + col) =
            packh2(oacc[nt][2] * inv1, oacc[nt][3] * inv1);
    }
#undef STAGE_KV
}

// ---------------------------------------------------------------------------
// Launch
// ---------------------------------------------------------------------------
extern "C" void kernel_launch(void* const* d_in, const int* in_sizes, int n_in,
                              void* d_out, int out_size)
{
    const float* input  = (const float*)d_in[0];
    const float* latent = (const float*)d_in[1];
    const int*   mask   = (const int*)d_in[2];
    const float* Wq = (const float*)d_in[3];
    const float* bq = (const float*)d_in[4];
    const float* Wk = (const float*)d_in[5];
    const float* bk = (const float*)d_in[6];
    const float* Wv = (const float*)d_in[7];
    const float* bv = (const float*)d_in[8];
    const float* Wo = (const float*)d_in[9];
    const float* bo = (const float*)d_in[10];
    float* out = (float*)d_out;

    void *qp, *kp, *vp, *op, *ah, *bhp, *wt;
    cudaGetSymbolAddress(&qp, g_Q);
    cudaGetSymbolAddress(&kp, g_K);
    cudaGetSymbolAddress(&vp, g_V);
    cudaGetSymbolAddress(&op, g_O);
    cudaGetSymbolAddress(&ah, g_Ah);
    cudaGetSymbolAddress(&bhp, g_Bh);
    cudaGetSymbolAddress(&wt, g_WT);
    __half* wqT = (__half*)wt + 0 * (size_t)LAT_ * LAT_;
    __half* wkT = (__half*)wt + 1 * (size_t)LAT_ * LAT_;
    __half* wvT = (__half*)wt + 2 * (size_t)LAT_ * LAT_;
    __half* woT = (__half*)wt + 3 * (size_t)LAT_ * LAT_;

    cudaFuncSetAttribute(gemm_f16<0>,
                         cudaFuncAttributeMaxDynamicSharedMemorySize, GEMM_SMEM);
    cudaFuncSetAttribute(gemm_f16<1>,
                         cudaFuncAttributeMaxDynamicSharedMemorySize, GEMM_SMEM);
    cudaFuncSetAttribute(gemm_f16<2>,
                         cudaFuncAttributeMaxDynamicSharedMemorySize, GEMM_SMEM);
    cudaFuncSetAttribute(attn_mma_kernel,
                         cudaFuncAttributeMaxDynamicSharedMemorySize, ATTN_SMEM);

    const int nact = B_ * S_ * LAT_;
    cvt_f16_kernel<<<nact / (256 * 8), 256>>>(latent, (__half*)ah);
    cvt_f16_kernel<<<nact / (256 * 8), 256>>>(input,  (__half*)bhp);
    dim3 tb(32, 8), tg(32, 32);
    transpose_cvt_kernel<<<tg, tb>>>(Wq, wqT);
    transpose_cvt_kernel<<<tg, tb>>>(Wk, wkT);
    transpose_cvt_kernel<<<tg, tb>>>(Wv, wvT);
    transpose_cvt_kernel<<<tg, tb>>>(Wo, woT);

    dim3 gg(LAT_ / 128, (B_ * S_) / 128);   // (8, 64)
    gemm_f16<1><<<gg, 256, GEMM_SMEM>>>((const __half*)ah,  wqT, bq, qp);
    gemm_f16<1><<<gg, 256, GEMM_SMEM>>>((const __half*)bhp, wkT, bk, kp);
    gemm_f16<2><<<gg, 256, GEMM_SMEM>>>((const __half*)bhp, wvT, bv, vp);

    dim3 ga(S_ / 128, B_ * H_);             // (8, 128)
    attn_mma_kernel<<<ga, 256, ATTN_SMEM>>>(mask, (__half*)op);

    gemm_f16<0><<<gg, 256, GEMM_SMEM>>>((const __half*)op, woT, bo, out);
}